// round 10
// baseline (speedup 1.0000x reference)
#include <cuda_runtime.h>
#include <cstdint>
#include <cstddef>

// Problem constants
#define SQ 2048      // sequence length
#define DK 2048      // d_model (GEMM K dim)
#define NB 2         // batch
#define NH 32        // q heads
#define NKV 8        // kv heads
#define HD 64        // head dim

// Scratch (device globals: no runtime allocation allowed)
__device__ float g_q [(size_t)NB * NH  * SQ * HD];   // [B,H,S,D]
__device__ float g_k [(size_t)NB * NKV * SQ * HD];   // [B,KV,S,D] (rope applied)
__device__ float g_v [(size_t)NB * NKV * SQ * HD];   // [B,KV,S,D]
__device__ float g_ao[(size_t)NB * SQ * NH * HD];    // [B,S,H*D]

// ---------------------------------------------------------------------------
// Packed f32x2 helpers (sm_103a: PTX-only FFMA2 path; the ONLY way to reach
// the full 128 fp32 FMA/cyc/SM on Blackwell)
// ---------------------------------------------------------------------------
__device__ __forceinline__ unsigned long long bcast2(float x) {
  unsigned long long r;
  unsigned int u = __float_as_uint(x);
  asm("mov.b64 %0, {%1, %1};" : "=l"(r) : "r"(u));
  return r;
}
__device__ __forceinline__ unsigned long long pack2(float x, float y) {
  unsigned long long r;
  asm("mov.b64 %0, {%1, %2};" : "=l"(r)
      : "r"(__float_as_uint(x)), "r"(__float_as_uint(y)));
  return r;
}
__device__ __forceinline__ void fma2(unsigned long long& d,
                                     unsigned long long a,
                                     unsigned long long b) {
  asm("fma.rn.f32x2 %0, %1, %2, %0;" : "+l"(d) : "l"(a), "l"(b));
}
__device__ __forceinline__ void mul2(unsigned long long& d,
                                     unsigned long long a) {
  asm("mul.rn.f32x2 %0, %0, %1;" : "+l"(d) : "l"(a));
}
__device__ __forceinline__ float2 unpack2(unsigned long long v) {
  unsigned int lo, hi;
  asm("mov.b64 {%0, %1}, %2;" : "=r"(lo), "=r"(hi) : "l"(v));
  return make_float2(__uint_as_float(lo), __uint_as_float(hi));
}

// ---------------------------------------------------------------------------
// GEMM: C[M=4096, N=64-per-block] = A[4096, 2048] @ W[2048, N]
// BM=128, BN=64, BK=16, 256 threads, 8x4 micro-tile per thread (f32x2 packed:
// 4 row-pairs x 4 cols = 16 FFMA2 per kk covering 32 FMAs).
// LDG.128 loaders + register prefetch + 2-stage smem double buffering
// (ONE __syncthreads per BK iteration instead of two).
// mode 0: plain row-major write to C (O projection), N = full row width
// mode 4: fused QKV — blockIdx.x in [0,32): Q (rope, ->Cq)
//                                  [32,40): K (rope, ->Ck)
//                                  [40,48): V (plain, ->Cv)
// BN == 64 == HEAD_DIM so each block covers exactly one head in mode 4.
// ---------------------------------------------------------------------------
struct GemmSmem {
  union {
    struct { float As[2][16][132]; float Bs[2][16][68]; } ab;  // As is [k][m]
    float Cs[128][65];                                          // epilogue staging
  };
};

__global__ void __launch_bounds__(256)
gemm128x64(const float* __restrict__ A,
           const float* __restrict__ Wq, const float* __restrict__ Wk,
           const float* __restrict__ Wv,
           float* __restrict__ Cq, float* __restrict__ Ck,
           float* __restrict__ Cv,
           const float* __restrict__ rc, const float* __restrict__ rs, int mode)
{
  __shared__ GemmSmem sm;
  const int tid = threadIdx.x;
  const int tx = tid & 15;        // 16 col-groups of 4
  const int ty = tid >> 4;        // 16 row-groups of 8
  const int m0 = blockIdx.y * 128;

  // route block -> (weight, output, head-count, rope, N)
  int hx = blockIdx.x;
  bool rope = false;
  const float* W = Wq;
  float* Cout = Cq;
  int H = NH;
  int N = 64 * gridDim.x;          // mode 0: full row width
  if (mode == 4) {
    if (hx < 32)      { W = Wq; Cout = Cq; H = NH;  rope = true;  N = 2048; }
    else if (hx < 40) { hx -= 32; W = Wk; Cout = Ck; H = NKV; rope = true;  N = 512; }
    else              { hx -= 40; W = Wv; Cout = Cv; H = NKV; rope = false; N = 512; }
  }
  const int n0 = hx * 64;

  // acc2[ip][j]: packed pair of rows (ty*8+2*ip, ty*8+2*ip+1), col tx*4+j
  unsigned long long acc2[4][4];
#pragma unroll
  for (int i = 0; i < 4; i++)
#pragma unroll
    for (int j = 0; j < 4; j++) acc2[i][j] = 0ull;

  // Vectorized loaders:
  // A: thread (row = tid>>2 in 0..63, kq = (tid&3)*4) loads 2 float4
  //    (rows row, row+64) per tile; stores 8 scalars (transposed layout).
  // B: thread (k = tid>>4, nq = (tid&15)*4) loads/stores 1 float4 per tile.
  const int aRow = tid >> 2;
  const int aKq  = (tid & 3) * 4;
  const int bK   = tid >> 4;
  const int bNq  = (tid & 15) * 4;

  const float* Aptr = A + (size_t)(m0 + aRow) * DK + aKq;
  const float* Bptr = W + (size_t)bK * N + n0 + bNq;

  // prefetch tile 0 into registers, commit to stage 0
  float4 av0 = *(const float4*)(Aptr);
  float4 av1 = *(const float4*)(Aptr + (size_t)64 * DK);
  float4 bv  = *(const float4*)(Bptr);

  sm.ab.As[0][aKq + 0][aRow] = av0.x;
  sm.ab.As[0][aKq + 1][aRow] = av0.y;
  sm.ab.As[0][aKq + 2][aRow] = av0.z;
  sm.ab.As[0][aKq + 3][aRow] = av0.w;
  sm.ab.As[0][aKq + 0][aRow + 64] = av1.x;
  sm.ab.As[0][aKq + 1][aRow + 64] = av1.y;
  sm.ab.As[0][aKq + 2][aRow + 64] = av1.z;
  sm.ab.As[0][aKq + 3][aRow + 64] = av1.w;
  *(float4*)&sm.ab.Bs[0][bK][bNq] = bv;
  __syncthreads();

  for (int it = 0; it < DK / 16; it++) {
    const int st = it & 1;          // compute stage
    const bool more = (it + 1) < DK / 16;

    // issue next tile's LDGs early (retire during compute below)
    if (more) {
      const int k0n = (it + 1) * 16;
      av0 = *(const float4*)(Aptr + k0n);
      av1 = *(const float4*)(Aptr + (size_t)64 * DK + k0n);
      bv  = *(const float4*)(Bptr + (size_t)k0n * N);
    }

#pragma unroll
    for (int kk = 0; kk < 16; kk++) {
      // A side: 8 rows as 4 packed pairs, directly from smem (LDS.128 x2)
      ulonglong2 aA = *(const ulonglong2*)&sm.ab.As[st][kk][ty * 8];
      ulonglong2 aB = *(const ulonglong2*)&sm.ab.As[st][kk][ty * 8 + 4];
      // B side: 4 scalars broadcast to pairs
      float4 b4 = *(const float4*)&sm.ab.Bs[st][kk][tx * 4];
      unsigned long long bb0 = bcast2(b4.x), bb1 = bcast2(b4.y);
      unsigned long long bb2 = bcast2(b4.z), bb3 = bcast2(b4.w);
      fma2(acc2[0][0], aA.x, bb0); fma2(acc2[0][1], aA.x, bb1);
      fma2(acc2[0][2], aA.x, bb2); fma2(acc2[0][3], aA.x, bb3);
      fma2(acc2[1][0], aA.y, bb0); fma2(acc2[1][1], aA.y, bb1);
      fma2(acc2[1][2], aA.y, bb2); fma2(acc2[1][3], aA.y, bb3);
      fma2(acc2[2][0], aB.x, bb0); fma2(acc2[2][1], aB.x, bb1);
      fma2(acc2[2][2], aB.x, bb2); fma2(acc2[2][3], aB.x, bb3);
      fma2(acc2[3][0], aB.y, bb0); fma2(acc2[3][1], aB.y, bb1);
      fma2(acc2[3][2], aB.y, bb2); fma2(acc2[3][3], aB.y, bb3);
    }

    // commit next tile to the other stage (prev readers fenced last iter)
    if (more) {
      const int sn = st ^ 1;
      sm.ab.As[sn][aKq + 0][aRow] = av0.x;
      sm.ab.As[sn][aKq + 1][aRow] = av0.y;
      sm.ab.As[sn][aKq + 2][aRow] = av0.z;
      sm.ab.As[sn][aKq + 3][aRow] = av0.w;
      sm.ab.As[sn][aKq + 0][aRow + 64] = av1.x;
      sm.ab.As[sn][aKq + 1][aRow + 64] = av1.y;
      sm.ab.As[sn][aKq + 2][aRow + 64] = av1.z;
      sm.ab.As[sn][aKq + 3][aRow + 64] = av1.w;
      *(float4*)&sm.ab.Bs[sn][bK][bNq] = bv;
    }
    __syncthreads();   // single barrier: fences this stage's reads + next's writes
  }

  if (mode == 0) {
#pragma unroll
    for (int i = 0; i < 4; i++) {
      const int m = m0 + ty * 8 + 2 * i;
#pragma unroll
      for (int j = 0; j < 4; j++) {
        float2 u = unpack2(acc2[i][j]);
        Cout[(size_t)m * N + n0 + tx * 4 + j] = u.x;
        Cout[(size_t)(m + 1) * N + n0 + tx * 4 + j] = u.y;
      }
    }
  } else if (!rope) {
    // plain scatter to [B, H, S, 64]
#pragma unroll
    for (int i = 0; i < 4; i++) {
      const int m = m0 + ty * 8 + 2 * i;
      const int bb = m >> 11, s = m & (SQ - 1);
#pragma unroll
      for (int j = 0; j < 4; j++) {
        const int d = tx * 4 + j;
        float2 u = unpack2(acc2[i][j]);
        Cout[(((size_t)bb * H + hx) * SQ + s) * HD + d] = u.x;
        Cout[(((size_t)bb * H + hx) * SQ + s + 1) * HD + d] = u.y;
      }
    }
  } else {
    // RoPE: needs the pair element (d ^ 32) -> stage tile through smem.
#pragma unroll
    for (int i = 0; i < 4; i++)
#pragma unroll
      for (int j = 0; j < 4; j++) {
        float2 u = unpack2(acc2[i][j]);
        sm.Cs[ty * 8 + 2 * i][tx * 4 + j] = u.x;
        sm.Cs[ty * 8 + 2 * i + 1][tx * 4 + j] = u.y;
      }
    __syncthreads();
#pragma unroll
    for (int i = 0; i < 8; i++) {
      const int m = m0 + ty * 8 + i;
      const int bb = m >> 11, s = m & (SQ - 1);
#pragma unroll
      for (int j = 0; j < 4; j++) {
        const int d = tx * 4 + j;
        const int jj = d & 31;
        const float c = rc[s * 32 + jj];
        const float sn = rs[s * 32 + jj];
        float res;
        if (d < 32)
          res = sm.Cs[ty * 8 + i][d] * c - sm.Cs[ty * 8 + i][d + 32] * sn;
        else
          res = sm.Cs[ty * 8 + i][d - 32] * sn + sm.Cs[ty * 8 + i][d] * c;
        Cout[(((size_t)bb * H + hx) * SQ + s) * HD + d] = res;
      }
    }
  }
}

// ---------------------------------------------------------------------------
// Flash attention (fp32, causal, online softmax), f32x2 packed inner loops.
// One block = 64 query rows of one (b, h); 64 threads, 1 query row/thread.
// smem: qs[64][68]  (q tile, row-major; stride 68 floats = 16B-aligned rows
//                    -> Q row read as 16 LDS.128 instead of 64 LDS.32)
//       kv[64][68]  (K tile TRANSPOSED ksT[d][c] during QK, then V[c][d] for
//                    PV; stride 68 keeps 16B alignment; compute reads are
//                    same-address broadcasts -> conflict-free)
// Probabilities live in registers (sc2, packed pairs); PV fully unrolled so
// sc2 stays register-indexed. smem total 34,816 B.
// ---------------------------------------------------------------------------
#define ATTN_SMEM_FLOATS (64 * 68 + 64 * 68)
#define ATTN_SMEM_BYTES  (ATTN_SMEM_FLOATS * 4)

__global__ void __launch_bounds__(64)
attn_kernel(const float* __restrict__ q, const float* __restrict__ k,
            const float* __restrict__ v, float* __restrict__ ao)
{
  extern __shared__ float smf[];
  float* qs = smf;                     // 64*68
  float* kv = smf + 64 * 68;           // 64*68

  const int t  = threadIdx.x;
  const int qt = gridDim.x - 1 - blockIdx.x;  // heavy tiles launch first
  const int h  = blockIdx.y;
  const int b  = blockIdx.z;
  const int s0 = qt * 64;

  const float* qbase = q + (((size_t)b * NH + h) * SQ + s0) * HD;
  const size_t kvoff = ((size_t)b * NKV + (h >> 2)) * SQ * HD;
  const float* kbase = k + kvoff;
  const float* vbase = v + kvoff;

  // load Q tile: qs[row][d] ; thread t supplies dim d = t for all rows
#pragma unroll 8
  for (int i = 0; i < 64; i++) qs[i * 68 + t] = qbase[i * HD + t];

  unsigned long long o2[32];           // output, packed pairs along d
#pragma unroll
  for (int i = 0; i < 32; i++) o2[i] = 0ull;
  float mprev = -1e30f, l = 0.f;
  const int rg = s0 + t;               // this thread's global query row

  for (int kt = 0; kt <= qt; kt++) {
    const int c0 = kt * 64;
    __syncthreads();   // previous PV done reading kv
    // K tile transposed: ksT[d=t][c=i]
#pragma unroll 8
    for (int i = 0; i < 64; i++) kv[t * 68 + i] = kbase[(size_t)(c0 + i) * HD + t];
    __syncthreads();

    // QK: sc packed pairs along c; Q row read as float4 (16B-aligned rows)
    unsigned long long sc2[32];
#pragma unroll
    for (int i = 0; i < 32; i++) sc2[i] = 0ull;
#pragma unroll 2
    for (int d4 = 0; d4 < 16; d4++) {
      const float4 qv = *(const float4*)(qs + t * 68 + d4 * 4);
      const float qsc[4] = {qv.x, qv.y, qv.z, qv.w};
#pragma unroll
      for (int du = 0; du < 4; du++) {
        const int d = d4 * 4 + du;
        const unsigned long long qq = bcast2(qsc[du]);
#pragma unroll
        for (int cc = 0; cc < 16; cc++) {
          ulonglong2 kp = *(const ulonglong2*)(kv + d * 68 + cc * 4);  // bcast
          fma2(sc2[cc * 2], kp.x, qq);
          fma2(sc2[cc * 2 + 1], kp.y, qq);
        }
      }
    }
    __syncthreads();   // everyone done reading ksT

    // overwrite kv with V tile: vs[c=i][d=t]
#pragma unroll 8
    for (int i = 0; i < 64; i++) kv[i * 68 + t] = vbase[(size_t)(c0 + i) * HD + t];

    // softmax pass A: mask+scale IN REGISTERS (sc2 in place), find max
    float mnew = mprev;
    if (kt == qt) {
#pragma unroll
      for (int pi = 0; pi < 32; pi++) {
        float2 s = unpack2(sc2[pi]);
        float a0 = (c0 + 2 * pi     <= rg) ? s.x * 0.125f : -1e30f;
        float a1 = (c0 + 2 * pi + 1 <= rg) ? s.y * 0.125f : -1e30f;
        sc2[pi] = pack2(a0, a1);
        mnew = fmaxf(mnew, fmaxf(a0, a1));
      }
    } else {
#pragma unroll
      for (int pi = 0; pi < 32; pi++) {
        float2 s = unpack2(sc2[pi]);
        float a0 = s.x * 0.125f, a1 = s.y * 0.125f;
        sc2[pi] = pack2(a0, a1);
        mnew = fmaxf(mnew, fmaxf(a0, a1));
      }
    }
    const float corr = __expf(mprev - mnew);
    l *= corr;
    const unsigned long long cc2 = bcast2(corr);
#pragma unroll
    for (int i = 0; i < 32; i++) mul2(o2[i], cc2);

    // softmax pass B: exp in registers, probs stay packed in sc2
    float lsum = 0.f;
#pragma unroll
    for (int pi = 0; pi < 32; pi++) {
      float2 s = unpack2(sc2[pi]);
      const float p0 = __expf(s.x - mnew);
      const float p1 = __expf(s.y - mnew);
      lsum += p0 + p1;
      sc2[pi] = pack2(p0, p1);
    }
    l += lsum;
    mprev = mnew;
    __syncthreads();       // V tile visible

    // PV: o[d] += p[c] * V[c][d]; probs from registers, fully unrolled so
    // sc2 stays register-indexed (no smem bounce, no spill)
#pragma unroll
    for (int pi = 0; pi < 32; pi++) {
      float2 pr = unpack2(sc2[pi]);
      const unsigned long long pp0 = bcast2(pr.x);
      const unsigned long long pp1 = bcast2(pr.y);
      const float* v0 = kv + (2 * pi) * 68;
      const float* v1 = kv + (2 * pi + 1) * 68;
#pragma unroll
      for (int dd = 0; dd < 16; dd++) {
        ulonglong2 vp = *(const ulonglong2*)(v0 + dd * 4);  // bcast
        fma2(o2[dd * 2], vp.x, pp0);
        fma2(o2[dd * 2 + 1], vp.y, pp0);
      }
#pragma unroll
      for (int dd = 0; dd < 16; dd++) {
        ulonglong2 vp = *(const ulonglong2*)(v1 + dd * 4);  // bcast
        fma2(o2[dd * 2], vp.x, pp1);
        fma2(o2[dd * 2 + 1], vp.y, pp1);
      }
    }
  }

  const float inv = 1.f / l;
  float* outp = ao + ((size_t)(b * SQ + s0 + t)) * (NH * HD) + h * HD;
#pragma unroll
  for (int pi = 0; pi < 32; pi++) {
    float2 u = unpack2(o2[pi]);
    *(float2*)(outp + 2 * pi) = make_float2(u.x * inv, u.y * inv);
  }
}

// ---------------------------------------------------------------------------
// Launch: fused QKV proj (1 launch) -> attention -> O proj
// ---------------------------------------------------------------------------
extern "C" void kernel_launch(void* const* d_in, const int* in_sizes, int n_in,
                              void* d_out, int out_size)
{
  const float* x  = (const float*)d_in[0];
  const float* Wq = (const float*)d_in[1];
  const float* Wk = (const float*)d_in[2];
  const float* Wv = (const float*)d_in[3];
  const float* Wo = (const float*)d_in[4];
  const float* rc = (const float*)d_in[5];
  const float* rs = (const float*)d_in[6];
  float* out = (float*)d_out;

  float *gq, *gk, *gv, *gao;
  cudaGetSymbolAddress((void**)&gq,  g_q);
  cudaGetSymbolAddress((void**)&gk,  g_k);
  cudaGetSymbolAddress((void**)&gv,  g_v);
  cudaGetSymbolAddress((void**)&gao, g_ao);

  cudaFuncSetAttribute(attn_kernel, cudaFuncAttributeMaxDynamicSharedMemorySize,
                       ATTN_SMEM_BYTES);

  // fused Q (rope) + K (rope) + V projections: 48 head-blocks x 32 m-tiles
  gemm128x64<<<dim3(48, 32), 256>>>(x, Wq, Wk, Wv, gq, gk, gv, rc, rs, 4);
  // attention: grid (q-tiles, heads, batch)
  attn_kernel<<<dim3(SQ / 64, NH, NB), 64, ATTN_SMEM_BYTES>>>(gq, gk, gv, gao);
  // output projection -> d_out (N = 64 * gridDim.x = 2048)
  gemm128x64<<<dim3(32, 32), 256>>>(gao, Wo, nullptr, nullptr, out, nullptr,
                                    nullptr, nullptr, nullptr, 0);
}